// round 11
// baseline (speedup 1.0000x reference)
#include <cuda_runtime.h>

// Shapes fixed by dataset: b=8, n=1024, m=2048, x_dim=1, c=3, Z=128
#define BB     8
#define NN     1024
#define MM     2048
#define MTB    64          // m-rows per block
#define KH     10          // Hermite terms k = 0..9
#define EPSV   1e-8f
#define LOG2E  1.4426950408889634f
#define K2     (-0.5f * LOG2E)   // exp(-u^2/2) = exp2(K2*u^2)

__device__ __forceinline__ float ex2f(float v) {
    float r;
    asm("ex2.approx.ftz.f32 %0, %1;" : "=f"(r) : "f"(v));
    return r;
}

// ---------------------------------------------------------------------------
// Fused kernel: 256 blocks x 384 threads (12 warps).
// Fast path (sigma uniform, scale~1):
//   A: stage scaled x', y, W, bias; zero unused red slots
//   B: 6 warps ballot-compact: 4 Hermite buckets on [-2,2) + 2 exact tail lists
//   C: 12 warps = (bucket, third-slice) moments, butterfly, store partials
//   D: 8 warps Hermite eval (center x rowgroup) + 4 warps exact tail eval
//   E: combine per row, normalize   F: project + store
// ---------------------------------------------------------------------------
__global__ __launch_bounds__(384)
void enc_fused(const float* __restrict__ x,
               const float* __restrict__ y,
               const float* __restrict__ t,
               const float* __restrict__ sigma,
               const float* __restrict__ W,
               const float* __restrict__ bfc,
               float* __restrict__ out)
{
    __shared__ float  sxp[NN];                 //  4 KB scaled x'
    __shared__ float2 sy[NN];                  //  8 KB y pairs
    __shared__ unsigned short bidxH[4][NN];    //  8 KB Hermite bucket lists
    __shared__ unsigned short tidx[2][NN];     //  4 KB tail lists (exact eval)
    __shared__ int    cnts[6];                 //  b0..b3 buckets, tailL, tailR
    __shared__ float  part[4][3][KH * 3];      //  1.4 KB moment partials
    __shared__ float4 red[12][MTB];            // 12 KB per-warp row partials
    __shared__ float4 zfin[MTB];               //  1 KB
    __shared__ float4 sW[96];                  //  1.5 KB
    __shared__ float4 sB[32];                  //  0.5 KB

    const int tid  = threadIdx.x;
    const int lane = tid & 31;
    const int wrp  = tid >> 5;          // 0..11
    const int blk  = blockIdx.x;
    const int b    = blk >> 5;          // 32 m-tiles per batch
    const int m_base = (blk & 31) * MTB;

    const float C0 = -0.5f * LOG2E * __expf(-2.f * sigma[0]);
    const float C1 = -0.5f * LOG2E * __expf(-2.f * sigma[1]);
    const float C2 = -0.5f * LOG2E * __expf(-2.f * sigma[2]);
    const float s  = __expf(sigma[0]);
    const bool fast = (C0 == C1) && (C0 == C2) && (s >= 0.8f) && (s <= 1.25f);

    // Stage W + bias (both paths)
    if (tid < 96)  sW[tid] = reinterpret_cast<const float4*>(W)[tid];
    if (tid >= 96 && tid < 128) sB[tid - 96] = reinterpret_cast<const float4*>(bfc)[tid - 96];

    if (fast) {
        const float s_inv = 1.f / s;

        // ---- A: stage scaled x', y; zero red[6..11] ----
        {
            const float*  xb = x + b * NN;
            const float2* yb = reinterpret_cast<const float2*>(y + b * NN * 2);
            for (int i = tid; i < NN; i += 384) {
                sxp[i] = __ldg(xb + i) * s_inv;
                sy[i]  = __ldg(yb + i);
            }
            red[6 + (tid >> 6)][tid & 63] = make_float4(0.f, 0.f, 0.f, 0.f);
        }
        __syncthreads();

        // ---- B: compaction. Warps 0-3: buckets [w-2, w-1); warp 4: x'<-2; warp 5: x'>=2 ----
        if (wrp < 6) {
            const float lo = (float)wrp - 2.f;
            const float hi = (float)wrp - 1.f;
            int cnt = 0;
            #pragma unroll 4
            for (int cb = 0; cb < NN; cb += 32) {
                float xv = sxp[cb + lane];
                bool sel;
                if (wrp < 4)       sel = (xv >= lo) && (xv < hi);
                else if (wrp == 4) sel = (xv < -2.f);
                else               sel = (xv >= 2.f);
                unsigned m = __ballot_sync(0xffffffffu, sel);
                if (sel) {
                    int pos = cnt + __popc(m & ((1u << lane) - 1u));
                    if (wrp < 4) bidxH[wrp][pos] = (unsigned short)(cb + lane);
                    else         tidx[wrp - 4][pos] = (unsigned short)(cb + lane);
                }
                cnt += __popc(m);
            }
            if (lane == 0) cnts[wrp] = cnt;
        }
        __syncthreads();

        // ---- C: moments. Warp w -> bucket wb = w/3, slice sl = w%3 ----
        {
            const int wb = wrp / 3;
            const int sl = wrp - 3 * wb;
            const int cnt = cnts[wb];
            const int jlo = (cnt * sl) / 3;
            const int jhi = (cnt * (sl + 1)) / 3;
            const float c = (float)wb - 1.5f;
            const float INVK[KH] = {0.f, 1.f, 0.5f, 1.f/3.f, 0.25f, 0.2f,
                                    1.f/6.f, 1.f/7.f, 0.125f, 1.f/9.f};

            float a0[KH], a1[KH], a2[KH];
            #pragma unroll
            for (int k = 0; k < KH; ++k) { a0[k] = 0.f; a1[k] = 0.f; a2[k] = 0.f; }

            for (int j = jlo + lane; j < jhi; j += 32) {
                int i = bidxH[wb][j];
                float  w_ = sxp[i] - c;
                float2 yv = sy[i];
                float p = 1.f;
                a0[0] += 1.f; a1[0] += yv.x; a2[0] += yv.y;
                #pragma unroll
                for (int k = 1; k < KH; ++k) {
                    p = p * w_ * INVK[k];
                    a0[k] += p;
                    a1[k] = fmaf(p, yv.x, a1[k]);
                    a2[k] = fmaf(p, yv.y, a2[k]);
                }
            }

            #pragma unroll
            for (int off = 16; off; off >>= 1) {
                #pragma unroll
                for (int k = 0; k < KH; ++k) {
                    a0[k] += __shfl_xor_sync(0xffffffffu, a0[k], off);
                    a1[k] += __shfl_xor_sync(0xffffffffu, a1[k], off);
                    a2[k] += __shfl_xor_sync(0xffffffffu, a2[k], off);
                }
            }
            if (lane == 0) {
                #pragma unroll
                for (int k = 0; k < KH; ++k) {
                    part[wb][sl][k * 3 + 0] = a0[k];
                    part[wb][sl][k * 3 + 1] = a1[k];
                    part[wb][sl][k * 3 + 2] = a2[k];
                }
            }
        }
        __syncthreads();

        // ---- D: evaluation ----
        if (wrp < 8) {
            // Hermite: center ci, rowgroup rg. Result slot = wrp (0..7).
            const int ci = wrp & 3;
            const int rg = wrp >> 2;
            const int row = rg * 32 + lane;
            const float c  = (float)ci - 1.5f;
            const float tr = __ldg(t + b * MM + m_base + row) * s_inv;
            const float u  = tr - c;
            const float E  = ex2f(K2 * u * u);

            float M0[KH], M1[KH], M2[KH];
            #pragma unroll
            for (int k = 0; k < KH; ++k) {      // warp-uniform broadcast LDS
                M0[k] = part[ci][0][k*3+0] + part[ci][1][k*3+0] + part[ci][2][k*3+0];
                M1[k] = part[ci][0][k*3+1] + part[ci][1][k*3+1] + part[ci][2][k*3+1];
                M2[k] = part[ci][0][k*3+2] + part[ci][1][k*3+2] + part[ci][2][k*3+2];
            }

            float Hk2 = E;                    // He_0 * E
            float s0 = M0[0] * Hk2;
            float s1 = M1[0] * Hk2;
            float s2 = M2[0] * Hk2;
            float Hk1 = u * E;                // He_1 * E
            s0 = fmaf(M0[1], Hk1, s0);
            s1 = fmaf(M1[1], Hk1, s1);
            s2 = fmaf(M2[1], Hk1, s2);
            #pragma unroll
            for (int k = 2; k < KH; ++k) {
                float Hk = fmaf(u, Hk1, -(float)(k - 1) * Hk2);
                s0 = fmaf(M0[k], Hk, s0);
                s1 = fmaf(M1[k], Hk, s1);
                s2 = fmaf(M2[k], Hk, s2);
                Hk2 = Hk1; Hk1 = Hk;
            }
            red[wrp][row] = make_float4(s0, s1, s2, 0.f);
        } else {
            // Exact tail: w8 = tailL rg0, w9 = tailL rg1, w10 = tailR rg0, w11 = tailR rg1.
            // Result slots 8..11 (distinct rows per slot pair; rows not covered stay 0).
            const int ti  = (wrp >= 10) ? 1 : 0;
            const int rg  = wrp & 1;
            const int row = rg * 32 + lane;
            const int cnt = cnts[4 + ti];
            const float tr = __ldg(t + b * MM + m_base + row) * s_inv;
            float s0 = 0.f, s1 = 0.f, s2 = 0.f;
            for (int j = 0; j < cnt; ++j) {          // warp-uniform broadcast reads
                int i = tidx[ti][j];
                float  d  = tr - sxp[i];
                float2 yv = sy[i];
                float e = ex2f(K2 * d * d);
                s0 += e;
                s1 = fmaf(e, yv.x, s1);
                s2 = fmaf(e, yv.y, s2);
            }
            red[wrp][row] = make_float4(s0, s1, s2, 0.f);
        }
    } else {
        // Exact direct fallback: warp wrp scans its n-slice for all 64 rows
        const int nstart = wrp * 86;
        const int nend   = min(NN, nstart + 86);
        const float*  xb = x + b * NN;
        const float2* yb = reinterpret_cast<const float2*>(y + b * NN * 2);
        #pragma unroll
        for (int rg = 0; rg < 2; ++rg) {
            const int row = rg * 32 + lane;
            const float tr = __ldg(t + b * MM + m_base + row);
            float s0 = 0.f, s1 = 0.f, s2 = 0.f;
            for (int i = nstart; i < nend; ++i) {
                float  d  = tr - __ldg(xb + i);
                float2 yv = __ldg(yb + i);
                float d2 = d * d;
                float e0 = ex2f(C0 * d2);
                float e1 = ex2f(C1 * d2);
                float e2 = ex2f(C2 * d2);
                s0 += e0;
                s1 = fmaf(e1, yv.x, s1);
                s2 = fmaf(e2, yv.y, s2);
            }
            red[wrp][row] = make_float4(s0, s1, s2, 0.f);
        }
    }
    __syncthreads();

    // ---- E: combine 12 slots per row, normalize ----
    if (tid < MTB) {
        float d0 = 0.f, d1 = 0.f, d2 = 0.f;
        #pragma unroll
        for (int wdx = 0; wdx < 12; ++wdx) {
            float4 p = red[wdx][tid];
            d0 += p.x; d1 += p.y; d2 += p.z;
        }
        float inv = 1.f / (d0 + EPSV);
        zfin[tid] = make_float4(d0, d1 * inv, d2 * inv, 0.f);
    }
    __syncthreads();

    // ---- F: out[b, m_base+row, :] = z @ W^T + bias ----
    float4* out4 = reinterpret_cast<float4*>(out);
    const size_t rowbase = (size_t)(b * MM + m_base);
    for (int j = tid; j < MTB * 32; j += 384) {
        const int row = j >> 5;
        const int k4  = j & 31;
        const float4 z  = zfin[row];
        const float4 wa = sW[3 * k4];
        const float4 wb = sW[3 * k4 + 1];
        const float4 wc = sW[3 * k4 + 2];
        const float4 bb = sB[k4];
        float4 o;
        o.x = fmaf(z.x, wa.x, fmaf(z.y, wa.y, fmaf(z.z, wa.z, bb.x)));
        o.y = fmaf(z.x, wa.w, fmaf(z.y, wb.x, fmaf(z.z, wb.y, bb.y)));
        o.z = fmaf(z.x, wb.z, fmaf(z.y, wb.w, fmaf(z.z, wc.x, bb.z)));
        o.w = fmaf(z.x, wc.y, fmaf(z.y, wc.z, fmaf(z.z, wc.w, bb.w)));
        out4[(rowbase + row) * 32 + k4] = o;
    }
}

extern "C" void kernel_launch(void* const* d_in, const int* in_sizes, int n_in,
                              void* d_out, int out_size)
{
    const float* x     = (const float*)d_in[0];   // (8,1024,1)
    const float* y     = (const float*)d_in[1];   // (8,1024,2)
    const float* t     = (const float*)d_in[2];   // (8,2048,1)
    const float* sigma = (const float*)d_in[3];   // (3,)
    const float* W     = (const float*)d_in[4];   // (128,3)
    const float* bfc   = (const float*)d_in[5];   // (128,)
    float* out = (float*)d_out;                   // (8,2048,128)

    enc_fused<<<BB * (MM / MTB), 384>>>(x, y, t, sigma, W, bfc, out);
}

// round 13
// speedup vs baseline: 1.3382x; 1.3382x over previous
#include <cuda_runtime.h>

// Shapes fixed by dataset: b=8, n=1024, m=2048, x_dim=1, c=3, Z=128
#define BB     8
#define NN     1024
#define MM     2048
#define MTB    128         // m-rows per block in main kernel (single wave: 128 blocks)
#define NCTR   12          // Hermite centers, c_l = l - 5.5, spacing 1
#define KH     10          // Hermite terms k = 0..9  (trunc err ~5e-7)
#define NMOM   (KH*3)      // 30 moments per (batch,center)
#define EPSV   1e-8f
#define LOG2E  1.4426950408889634f
#define K2     (-0.5f * LOG2E)   // exp(-u^2/2) = exp2(K2*u^2)

// Scratch: moments M[b][ctr][k][ch]
__device__ float g_moments[BB * NCTR * NMOM];

__device__ __forceinline__ float ex2f(float v) {
    float r;
    asm("ex2.approx.ftz.f32 %0, %1;" : "=f"(r) : "f"(v));
    return r;
}

// ---------------------------------------------------------------------------
// Kernel 1: moments. One block (128 thr = 4 warps) per (batch,center).
// Each warp scans a 256-point quarter (8 iters/lane), butterfly-reduces its
// 30 accumulators, then 4 warp-partials combine through smem. No atomics.
// ---------------------------------------------------------------------------
__global__ __launch_bounds__(128)
void moments_kernel(const float* __restrict__ x,
                    const float* __restrict__ y,
                    const float* __restrict__ sigma)
{
    __shared__ float cm[4][NMOM];

    const int tid  = threadIdx.x;
    const int lane = tid & 31;
    const int wrp  = tid >> 5;
    const int b    = blockIdx.x / NCTR;
    const int ctr  = blockIdx.x % NCTR;
    const float c  = (float)ctr - 5.5f;

    const float s_inv = __expf(-sigma[0]);   // 1/scale

    const float INVK[KH] = {0.f, 1.f, 0.5f, 1.f/3.f, 0.25f, 0.2f,
                            1.f/6.f, 1.f/7.f, 0.125f, 1.f/9.f};

    float a0[KH], a1[KH], a2[KH];
    #pragma unroll
    for (int k = 0; k < KH; ++k) { a0[k] = 0.f; a1[k] = 0.f; a2[k] = 0.f; }

    const float*  xb = x + b * NN;
    const float2* yb = reinterpret_cast<const float2*>(y + b * NN * 2);

    const int ibase = wrp * (NN / 4);
    #pragma unroll
    for (int ii = 0; ii < NN / 128; ++ii) {          // 8 iters per lane
        const int i = ibase + ii * 32 + lane;
        float xv = __ldg(xb + i) * s_inv;
        int l = (int)floorf(xv + 6.0f);
        l = min(max(l, 0), NCTR - 1);
        if (l == ctr) {
            float2 yv = __ldg(yb + i);
            float w = xv - c;
            float p = 1.f;
            a0[0] += 1.f; a1[0] += yv.x; a2[0] += yv.y;
            #pragma unroll
            for (int k = 1; k < KH; ++k) {
                p = p * w * INVK[k];
                a0[k] += p;
                a1[k] = fmaf(p, yv.x, a1[k]);
                a2[k] = fmaf(p, yv.y, a2[k]);
            }
        }
    }

    // Warp butterfly (30 accumulators)
    #pragma unroll
    for (int off = 16; off; off >>= 1) {
        #pragma unroll
        for (int k = 0; k < KH; ++k) {
            a0[k] += __shfl_xor_sync(0xffffffffu, a0[k], off);
            a1[k] += __shfl_xor_sync(0xffffffffu, a1[k], off);
            a2[k] += __shfl_xor_sync(0xffffffffu, a2[k], off);
        }
    }

    if (lane == 0) {
        #pragma unroll
        for (int k = 0; k < KH; ++k) {
            cm[wrp][k * 3 + 0] = a0[k];
            cm[wrp][k * 3 + 1] = a1[k];
            cm[wrp][k * 3 + 2] = a2[k];
        }
    }
    __syncthreads();

    if (tid < NMOM)
        g_moments[(b * NCTR + ctr) * NMOM + tid] =
            cm[0][tid] + cm[1][tid] + cm[2][tid] + cm[3][tid];
}

// ---------------------------------------------------------------------------
// Kernel 2: 128 blocks x 384 threads -> ONE wave on 148 SMs.
// Warp = center (0..11); 4 rowgroups of 32 rows each (MTB=128).
// Moments + W + bias staged in smem once per block.
// ---------------------------------------------------------------------------
__global__ __launch_bounds__(384)
void main_kernel(const float* __restrict__ x,
                 const float* __restrict__ y,
                 const float* __restrict__ t,
                 const float* __restrict__ sigma,
                 const float* __restrict__ W,
                 const float* __restrict__ bfc,
                 float* __restrict__ out)
{
    __shared__ float  sM[NCTR * NMOM];   // 360 floats
    __shared__ float4 sW[96];
    __shared__ float4 sB[32];
    __shared__ float4 red[NCTR][MTB];    // 24 KB
    __shared__ float4 zfin[MTB];         //  2 KB

    const int tid  = threadIdx.x;
    const int lane = tid & 31;
    const int wrp  = tid >> 5;          // 0..11 = center (fast) / n-slice (fallback)
    const int blk  = blockIdx.x;
    const int b    = blk >> 4;          // 16 m-tiles per batch
    const int m_base = (blk & 15) * MTB;

    const float C0 = -0.5f * LOG2E * __expf(-2.f * sigma[0]);
    const float C1 = -0.5f * LOG2E * __expf(-2.f * sigma[1]);
    const float C2 = -0.5f * LOG2E * __expf(-2.f * sigma[2]);
    const float s  = __expf(sigma[0]);
    const bool fast = (C0 == C1) && (C0 == C2) && (s >= 0.8f) && (s <= 1.25f);

    // Stage W + bias + moments in shared (careful, 384 threads total)
    if (tid < 96) sW[tid] = reinterpret_cast<const float4*>(W)[tid];
    else if (tid < 128) sB[tid - 96] = reinterpret_cast<const float4*>(bfc)[tid - 96];
    for (int i = tid; i < NCTR * NMOM; i += 384)
        sM[i] = g_moments[b * (NCTR * NMOM) + i];
    __syncthreads();

    if (fast) {
        const float s_inv = 1.f / s;
        const float c     = (float)wrp - 5.5f;
        const float* Mc   = sM + wrp * NMOM;

        #pragma unroll
        for (int rg = 0; rg < 4; ++rg) {
            const int row = rg * 32 + lane;
            const float tr = __ldg(t + b * MM + m_base + row) * s_inv;
            const float u  = tr - c;
            const float E  = ex2f(K2 * u * u);

            float Hk2 = E;                    // He_0 * E
            float s0 = Mc[0] * Hk2;
            float s1 = Mc[1] * Hk2;
            float s2 = Mc[2] * Hk2;
            float Hk1 = u * E;                // He_1 * E
            s0 = fmaf(Mc[3], Hk1, s0);
            s1 = fmaf(Mc[4], Hk1, s1);
            s2 = fmaf(Mc[5], Hk1, s2);
            #pragma unroll
            for (int k = 2; k < KH; ++k) {
                float Hk = fmaf(u, Hk1, -(float)(k - 1) * Hk2);  // He recurrence * E
                s0 = fmaf(Mc[k * 3 + 0], Hk, s0);
                s1 = fmaf(Mc[k * 3 + 1], Hk, s1);
                s2 = fmaf(Mc[k * 3 + 2], Hk, s2);
                Hk2 = Hk1; Hk1 = Hk;
            }
            red[wrp][row] = make_float4(s0, s1, s2, 0.f);
        }
    } else {
        // Exact direct fallback: warp wrp scans its n-slice for all 128 rows
        const int nstart = wrp * 86;
        const int nend   = min(NN, nstart + 86);
        const float*  xb = x + b * NN;
        const float2* yb = reinterpret_cast<const float2*>(y + b * NN * 2);
        #pragma unroll
        for (int rg = 0; rg < 4; ++rg) {
            const int row = rg * 32 + lane;
            const float tr = __ldg(t + b * MM + m_base + row);
            float s0 = 0.f, s1 = 0.f, s2 = 0.f;
            for (int i = nstart; i < nend; ++i) {
                float  d  = tr - __ldg(xb + i);
                float2 yv = __ldg(yb + i);
                float d2 = d * d;
                float e0 = ex2f(C0 * d2);
                float e1 = ex2f(C1 * d2);
                float e2 = ex2f(C2 * d2);
                s0 += e0;
                s1 = fmaf(e1, yv.x, s1);
                s2 = fmaf(e2, yv.y, s2);
            }
            red[wrp][row] = make_float4(s0, s1, s2, 0.f);
        }
    }
    __syncthreads();

    // Combine 12 center/slice partials per row, normalize (128 threads)
    if (tid < MTB) {
        float d0 = 0.f, d1 = 0.f, d2 = 0.f;
        #pragma unroll
        for (int wdx = 0; wdx < NCTR; ++wdx) {
            float4 p = red[wdx][tid];
            d0 += p.x; d1 += p.y; d2 += p.z;
        }
        float inv = 1.f / (d0 + EPSV);
        zfin[tid] = make_float4(d0, d1 * inv, d2 * inv, 0.f);
    }
    __syncthreads();

    // Epilogue: 128 rows x 32 col-groups = 4096 float4 stores over 384 threads
    float4* out4 = reinterpret_cast<float4*>(out);
    const size_t rowbase = (size_t)(b * MM + m_base);
    for (int j = tid; j < MTB * 32; j += 384) {
        const int row = j >> 5;
        const int k4  = j & 31;
        const float4 z  = zfin[row];
        const float4 wa = sW[3 * k4];
        const float4 wb = sW[3 * k4 + 1];
        const float4 wc = sW[3 * k4 + 2];
        const float4 bb = sB[k4];
        float4 o;
        o.x = fmaf(z.x, wa.x, fmaf(z.y, wa.y, fmaf(z.z, wa.z, bb.x)));
        o.y = fmaf(z.x, wa.w, fmaf(z.y, wb.x, fmaf(z.z, wb.y, bb.y)));
        o.z = fmaf(z.x, wb.z, fmaf(z.y, wb.w, fmaf(z.z, wc.x, bb.z)));
        o.w = fmaf(z.x, wc.y, fmaf(z.y, wc.z, fmaf(z.z, wc.w, bb.w)));
        out4[(rowbase + row) * 32 + k4] = o;
    }
}

extern "C" void kernel_launch(void* const* d_in, const int* in_sizes, int n_in,
                              void* d_out, int out_size)
{
    const float* x     = (const float*)d_in[0];   // (8,1024,1)
    const float* y     = (const float*)d_in[1];   // (8,1024,2)
    const float* t     = (const float*)d_in[2];   // (8,2048,1)
    const float* sigma = (const float*)d_in[3];   // (3,)
    const float* W     = (const float*)d_in[4];   // (128,3)
    const float* bfc   = (const float*)d_in[5];   // (128,)
    float* out = (float*)d_out;                   // (8,2048,128)

    moments_kernel<<<BB * NCTR, 128>>>(x, y, sigma);
    main_kernel<<<BB * (MM / MTB), 384>>>(x, y, t, sigma, W, bfc, out);
}